// round 6
// baseline (speedup 1.0000x reference)
#include <cuda_runtime.h>

#define T_STEPS 784
#define HDIM    110
#define NTH     448
#define NCLS    10

// ---------- f32x2 packed helpers ----------
__device__ __forceinline__ unsigned long long pk2(float x, float y) {
    unsigned long long r;
    asm("mov.b64 %0, {%1,%2};" : "=l"(r) : "f"(x), "f"(y));
    return r;
}
__device__ __forceinline__ float2 upk2(unsigned long long a) {
    float2 r;
    asm("mov.b64 {%0,%1}, %2;" : "=f"(r.x), "=f"(r.y) : "l"(a));
    return r;
}
__device__ __forceinline__ void ff2(unsigned long long& acc,
                                    unsigned long long a,
                                    unsigned long long b) {
    asm("fma.rn.f32x2 %0, %1, %2, %0;" : "+l"(acc) : "l"(a), "l"(b));
}

// ---------- activations ----------
__device__ __forceinline__ float tanha(float x) {          // MUFU.TANH
    float r;
    asm("tanh.approx.f32 %0, %1;" : "=f"(r) : "f"(x));
    return r;
}
__device__ __forceinline__ float sigmf(float x) {          // fast gate sigmoid
    return fmaf(0.5f, tanha(0.5f * x), 0.5f);
}
__device__ __forceinline__ float sigm_precise(float x) {   // du decision path
    return __fdividef(1.0f, 1.0f + __expf(-x));
}

__global__ void zero_slot_kernel(float* o, int idx) { o[idx] = 0.0f; }

__global__ void __launch_bounds__(NTH, 1) skiplstm_kernel(
    const float* __restrict__ x,      // [B, T, 1]
    const float* __restrict__ Wih,    // [440, 1]
    const float* __restrict__ Whh,    // [440, 110]
    const float* __restrict__ bg,     // [440]
    const float* __restrict__ Wp,     // [1, 110]
    const float* __restrict__ bp_,    // [1]
    const float* __restrict__ h0,     // [110]
    const float* __restrict__ c0,     // [110]
    const float* __restrict__ Wfc,    // [10, 110]
    const float* __restrict__ bfc,    // [10]
    float* __restrict__ out,          // [B*10 + 1]
    int last_idx)
{
    __shared__ float sx[2][T_STEPS];                    // x sequences
    __shared__ __align__(16) float hbuf[2][2][112];     // [buf][batch][dim] h
    __shared__ __align__(16) float cbuf[2][2][112];     // [buf][batch][dim] c
    __shared__ __align__(16) float part[2][2][16];      // [buf][batch][warp] du partials
    __shared__ float swp[112];                          // W_p (zero-padded)

    const int tid  = threadIdx.x;
    const int warp = tid >> 5, lane = tid & 31;
    const int g    = lane >> 3, dd = lane & 7;
    const int d    = warp * 8 + dd;                     // my hidden dim
    const bool valid = (d < HDIM);
    const int b0g  = blockIdx.x * 2;

    for (int i = tid; i < T_STEPS; i += NTH) {
        sx[0][i] = x[b0g * T_STEPS + i];
        sx[1][i] = x[(b0g + 1) * T_STEPS + i];
    }
    for (int i = tid; i < 112; i += NTH) {
        float hv = (i < HDIM) ? h0[i] : 0.0f;
        float cv = (i < HDIM) ? c0[i] : 0.0f;
        hbuf[0][0][i] = hv; hbuf[0][1][i] = hv;
        hbuf[1][0][i] = 0.0f; hbuf[1][1][i] = 0.0f;     // pads stay 0 forever
        cbuf[0][0][i] = cv; cbuf[0][1][i] = cv;
        cbuf[1][0][i] = 0.0f; cbuf[1][1][i] = 0.0f;
        swp[i] = (i < HDIM) ? Wp[i] : 0.0f;
    }
    if (tid < 64) ((float*)part)[tid] = 0.0f;           // entries 14,15 stay 0

    // my gate row: row = g*110 + d  (gate-major, matches i,f,g,o split)
    const int row = g * HDIM + (valid ? d : 0);
    unsigned long long w[55];
    {
        const float* wr = Whh + row * HDIM;
#pragma unroll
        for (int k = 0; k < 55; k++)
            w[k] = valid ? pk2(wr[2 * k], wr[2 * k + 1]) : 0ull;
    }
    const float wihv = valid ? Wih[row] : 0.0f;
    const float bjv  = valid ? bg[row]  : 0.0f;
    const float bp   = bp_[0];
    __syncthreads();

    float u0 = 1.0f, u1 = 1.0f;
    bool  a0 = true, a1 = true;
    int   totu = 0;

    for (int t = 0; t < T_STEPS; t++) {
        const int r  = t & 1;          // read buffer
        const int wb = r ^ 1;          // write buffer

        // ---- u/flag chain (redundant per-thread; identical & deterministic) ----
        if (t > 0) {
            const float4* p0 = (const float4*)part[r][0];
            const float4* p1 = (const float4*)part[r][1];
            float4 A = p0[0], B = p0[1], C = p0[2], D = p0[3];
            float dot0 = ((A.x + A.y) + (A.z + A.w)) + ((B.x + B.y) + (B.z + B.w))
                       + ((C.x + C.y) + (C.z + C.w)) + ((D.x + D.y) + (D.z + D.w));
            A = p1[0]; B = p1[1]; C = p1[2]; D = p1[3];
            float dot1 = ((A.x + A.y) + (A.z + A.w)) + ((B.x + B.y) + (B.z + B.w))
                       + ((C.x + C.y) + (C.z + C.w)) + ((D.x + D.y) + (D.z + D.w));
            float du0 = sigm_precise(dot0 + bp);
            float du1 = sigm_precise(dot1 + bp);
            u0 = a0 ? du0 : u0 + fminf(du0, 1.0f - u0);
            u1 = a1 ? du1 : u1 + fminf(du1, 1.0f - u1);
            a0 = (rintf(u0) != 0.0f);
            a1 = (rintf(u1) != 0.0f);
        }
        totu += (a0 ? 1 : 0) + (a1 ? 1 : 0);

        // ---- GEMV: my gate row x both batch lanes (interleaved chains) ----
        const ulonglong2* hq0 = (const ulonglong2*)hbuf[r][0];
        const ulonglong2* hq1 = (const ulonglong2*)hbuf[r][1];
        unsigned long long ax0 = 0ull, ay0 = 0ull, ax1 = 0ull, ay1 = 0ull;
#pragma unroll
        for (int k = 0; k < 27; k++) {
            ulonglong2 c0v = hq0[k];
            ulonglong2 c1v = hq1[k];
            ff2(ax0, w[2 * k],     c0v.x);
            ff2(ay0, w[2 * k + 1], c0v.y);
            ff2(ax1, w[2 * k],     c1v.x);
            ff2(ay1, w[2 * k + 1], c1v.y);
        }
        {
            unsigned long long t0 = ((const unsigned long long*)hbuf[r][0])[54];
            unsigned long long t1 = ((const unsigned long long*)hbuf[r][1])[54];
            ff2(ax0, w[54], t0);
            ff2(ax1, w[54], t1);
        }
        float2 vx0 = upk2(ax0), vy0 = upk2(ay0);
        float2 vx1 = upk2(ax1), vy1 = upk2(ay1);
        float val0 = (vx0.x + vx0.y) + (vy0.x + vy0.y) + fmaf(sx[0][t], wihv, bjv);
        float val1 = (vx1.x + vx1.y) + (vy1.x + vy1.y) + fmaf(sx[1][t], wihv, bjv);

        // ---- gate exchange: warp-local (4 gates of dim d live at dd+8g) ----
        float i0 = __shfl_sync(0xffffffffu, val0, dd);
        float f0 = __shfl_sync(0xffffffffu, val0, dd + 8);
        float g0 = __shfl_sync(0xffffffffu, val0, dd + 16);
        float o0 = __shfl_sync(0xffffffffu, val0, dd + 24);
        float i1 = __shfl_sync(0xffffffffu, val1, dd);
        float f1 = __shfl_sync(0xffffffffu, val1, dd + 8);
        float g1 = __shfl_sync(0xffffffffu, val1, dd + 16);
        float o1 = __shfl_sync(0xffffffffu, val1, dd + 24);

        // ---- pointwise: lanes g==0 handle batch0, g==1 batch1 ----
        const int  bsel = g & 1;
        const bool act  = bsel ? a1 : a0;
        float ii = bsel ? i1 : i0, ff = bsel ? f1 : f0;
        float gg = bsel ? g1 : g0, oo = bsel ? o1 : o0;
        float c_old = cbuf[r][bsel][d];
        float h_old = hbuf[r][bsel][d];
        float i_ = sigmf(ii), f_ = sigmf(ff), gv_ = tanha(gg), o_ = sigmf(oo);
        float cnn = f_ * c_old + i_ * gv_;
        float cn  = act ? cnn : c_old;
        float hn  = act ? (o_ * tanha(cnn)) : h_old;

        float p = (g < 2) ? cn * swp[d] : 0.0f;         // swp[d]=0 for d>=110
        p += __shfl_xor_sync(0xffffffffu, p, 1);
        p += __shfl_xor_sync(0xffffffffu, p, 2);
        p += __shfl_xor_sync(0xffffffffu, p, 4);

        if (g < 2 && valid) {
            cbuf[wb][bsel][d] = cn;
            hbuf[wb][bsel][d] = hn;
        }
        if (dd == 0 && g < 2) part[wb][bsel][warp] = p;

        __syncthreads();                                // the ONLY bar per step
    }

    // ---- FC head: final h is in buf 0 (t=783 wrote wb=0) ----
    for (int pi = warp; pi < 2 * NCLS; pi += NTH / 32) {
        const int b = pi / NCLS, cls = pi % NCLS;
        const float* wf = Wfc + cls * HDIM;
        float s = 0.0f;
        for (int dim = lane; dim < HDIM; dim += 32) s += hbuf[0][b][dim] * wf[dim];
#pragma unroll
        for (int off = 16; off; off >>= 1)
            s += __shfl_xor_sync(0xffffffffu, s, off);
        if (lane == 0) out[(b0g + b) * NCLS + cls] = s + bfc[cls];
    }

    if (tid == 0) atomicAdd(&out[last_idx], (float)totu);
}

extern "C" void kernel_launch(void* const* d_in, const int* in_sizes, int n_in,
                              void* d_out, int out_size) {
    const float* x    = (const float*)d_in[0];
    const float* Wih  = (const float*)d_in[1];
    const float* Whh  = (const float*)d_in[2];
    const float* bg   = (const float*)d_in[3];
    const float* Wp   = (const float*)d_in[4];
    const float* bp   = (const float*)d_in[5];
    const float* h0   = (const float*)d_in[6];
    const float* c0   = (const float*)d_in[7];
    const float* Wfc  = (const float*)d_in[8];
    const float* bfc  = (const float*)d_in[9];
    float* out = (float*)d_out;

    const int B = in_sizes[0] / T_STEPS;   // I = 1
    const int last = out_size - 1;

    zero_slot_kernel<<<1, 1>>>(out, last);
    skiplstm_kernel<<<B / 2, NTH>>>(x, Wih, Whh, bg, Wp, bp, h0, c0,
                                    Wfc, bfc, out, last);
}